// round 1
// baseline (speedup 1.0000x reference)
#include <cuda_runtime.h>
#include <math.h>

// LIFNeuron: spike( dopri5(x; dx = gelu(xW) * 1/(1+sigmoid(xWg+bg)), 8 fixed steps) - 0.3 )
//
// Block = 128 rows, 512 threads. State tiles stored [dim][row] (64 x 128 f32) in smem.
// Tiles 0..4 = stage states 2..6 ("S_i"), tile 5 = running x_new ("XN", doubles as
// stage-7 state and next-step base x, FSAL). W|Wg fused side-by-side as [64][128].

#define DIM 64
#define TROWS 128
#define NTHREADS 512
#define TILE_FLOATS (DIM * 128)            // 8192 floats per tile
#define SMEM_FLOATS (TILE_FLOATS * 7)      // WG + 6 state tiles
#define SMEM_BYTES  (SMEM_FLOATS * 4)      // 229376 bytes

// h = 1/8 (exact), coefficients rounded to fp32 exactly as numpy float32 does,
// then scaled by the exact power of two: matches reference h*float(A[i,j]).

// Stage-0 epilogue coefficients: k0 -> S1..S5 (tiles 0..4) and XN (b0)
__constant__ float c_s0[6] = {
    0.125f * (float)(1.0/5.0),
    0.125f * (float)(3.0/40.0),
    0.125f * (float)(44.0/45.0),
    0.125f * (float)(19372.0/6561.0),
    0.125f * (float)(9017.0/3168.0),
    0.125f * (float)(35.0/384.0)
};

// Stages 1..5: flattened (target tile, coefficient) lists.
// stage1: k1 -> tiles 1,2,3,4            (b1 = 0)
// stage2: k2 -> tiles 2,3,4, XN
// stage3: k3 -> tiles 3,4, XN
// stage4: k4 -> tiles 4, XN
// stage5: k5 -> XN
__constant__ int c_tgt_tile[14] = {1,2,3,4, 2,3,4,5, 3,4,5, 4,5, 5};
__constant__ float c_tgt_coef[14] = {
    0.125f * (float)(9.0/40.0),
    0.125f * (float)(-56.0/15.0),
    0.125f * (float)(-25360.0/2187.0),
    0.125f * (float)(-355.0/33.0),

    0.125f * (float)(32.0/9.0),
    0.125f * (float)(64448.0/6561.0),
    0.125f * (float)(46732.0/5247.0),
    0.125f * (float)(500.0/1113.0),

    0.125f * (float)(-212.0/729.0),
    0.125f * (float)(49.0/176.0),
    0.125f * (float)(125.0/192.0),

    0.125f * (float)(-5103.0/18656.0),
    0.125f * (float)(-2187.0/6784.0),

    0.125f * (float)(11.0/84.0)
};
__constant__ int c_seg[6] = {0, 4, 8, 11, 13, 14};   // stage j uses [c_seg[j-1], c_seg[j])

// One dynamics evaluation for this thread's 4-row x 4-col microtile:
// GEMM [4 rows x 64] @ [64 x (4 u-cols + 4 v-cols)], then k = gelu(u) * 1/(1+sigmoid(v+bg)).
// kv[jj][i] = k value at dim (c0+jj), row (r0+i).
__device__ __forceinline__ void dyn_stage(const float* src, const float* wg,
                                          const float* bgr, int r0, int c0,
                                          float kv[4][4])
{
    float au[4][4], av[4][4];
#pragma unroll
    for (int i = 0; i < 4; ++i)
#pragma unroll
        for (int j = 0; j < 4; ++j) { au[i][j] = 0.f; av[i][j] = 0.f; }

    const float* pa = src + r0;
    const float* pu = wg + c0;
    const float* pv = wg + 64 + c0;
#pragma unroll 4
    for (int k = 0; k < DIM; ++k) {
        float4 a  = *reinterpret_cast<const float4*>(pa + (k << 7));
        float4 bu = *reinterpret_cast<const float4*>(pu + (k << 7));
        float4 bv = *reinterpret_cast<const float4*>(pv + (k << 7));
        float ar[4] = {a.x, a.y, a.z, a.w};
        float ur[4] = {bu.x, bu.y, bu.z, bu.w};
        float vr[4] = {bv.x, bv.y, bv.z, bv.w};
#pragma unroll
        for (int i = 0; i < 4; ++i)
#pragma unroll
            for (int j = 0; j < 4; ++j) {
                au[i][j] = fmaf(ar[i], ur[j], au[i][j]);
                av[i][j] = fmaf(ar[i], vr[j], av[i][j]);
            }
    }
#pragma unroll
    for (int j = 0; j < 4; ++j) {
        const float b = bgr[j];
#pragma unroll
        for (int i = 0; i < 4; ++i) {
            float u = au[i][j];
            float v = av[i][j] + b;
            float e  = expf(-v);
            float s  = 1.f / (1.f + e);          // sigmoid(v)
            float tf = 1.f / (1.f + s);          // time factor
            float g  = 0.5f * (u * (erff(u * 0.70710678118654752440f) + 1.f)); // exact gelu
            kv[j][i] = g * tf;
        }
    }
}

__global__ void __launch_bounds__(NTHREADS, 1)
lif_dopri5_kernel(const float* __restrict__ gx, const float* __restrict__ gW,
                  const float* __restrict__ gWg, const float* __restrict__ gbg,
                  float* __restrict__ gout, int batch)
{
    extern __shared__ float smem[];
    float* WG = smem;                           // [64][128] : cols 0..63 = W, 64..127 = Wg
    float* tiles0 = smem + TILE_FLOATS;         // 6 state tiles, [dim][row]
    float* XN = tiles0 + 5 * TILE_FLOATS;

    const int t  = threadIdx.x;
    const int c0 = (t >> 5) << 2;               // 4 dims per thread (warp-uniform)
    const int r0 = (t & 31) << 2;               // 4 rows per thread (lane-spread -> conflict-free LDS.128)
    const int row0 = blockIdx.x * TROWS;

    // Load fused weight tile
    for (int idx = t; idx < DIM * 128; idx += NTHREADS) {
        int k = idx >> 7, c = idx & 127;
        WG[idx] = (c < DIM) ? gW[k * DIM + c] : gWg[k * DIM + (c - DIM)];
    }
    // Gate bias for this thread's 4 dims
    float bgr[4];
    {
        float4 b4 = reinterpret_cast<const float4*>(gbg)[c0 >> 2];
        bgr[0] = b4.x; bgr[1] = b4.y; bgr[2] = b4.z; bgr[3] = b4.w;
    }
    // Load x (transposed) into XN
    for (int idx = t; idx < TROWS * DIM; idx += NTHREADS) {
        int r = idx >> 6, c = idx & 63;
        int row = row0 + r;
        XN[(c << 7) + r] = (row < batch) ? gx[row * DIM + c] : 0.f;
    }
    __syncthreads();

    float kv[4][4];
    // k0 at t = 0 (FSAL seed)
    dyn_stage(XN, WG, bgr, r0, c0, kv);
    __syncthreads();

    for (int step = 0; step < 8; ++step) {
        // ---- stage-0 epilogue: S_i = x + h*a_i0*k0 (i=1..5), XN = x + h*b0*k0 (in place) ----
#pragma unroll
        for (int jj = 0; jj < 4; ++jj) {
            const int off = ((c0 + jj) << 7) + r0;
            float4 x4 = *reinterpret_cast<float4*>(XN + off);
#pragma unroll
            for (int m = 0; m < 5; ++m) {
                const float cf = c_s0[m];
                float4 tv;
                tv.x = fmaf(cf, kv[jj][0], x4.x);
                tv.y = fmaf(cf, kv[jj][1], x4.y);
                tv.z = fmaf(cf, kv[jj][2], x4.z);
                tv.w = fmaf(cf, kv[jj][3], x4.w);
                *reinterpret_cast<float4*>(tiles0 + m * TILE_FLOATS + off) = tv;
            }
            {
                const float cf = c_s0[5];
                float4 tv;
                tv.x = fmaf(cf, kv[jj][0], x4.x);
                tv.y = fmaf(cf, kv[jj][1], x4.y);
                tv.z = fmaf(cf, kv[jj][2], x4.z);
                tv.w = fmaf(cf, kv[jj][3], x4.w);
                *reinterpret_cast<float4*>(XN + off) = tv;
            }
        }
        __syncthreads();

        // ---- stages 1..5 ----
        for (int j = 1; j <= 5; ++j) {
            dyn_stage(tiles0 + (j - 1) * TILE_FLOATS, WG, bgr, r0, c0, kv);
            const int m1 = c_seg[j];
            for (int m = c_seg[j - 1]; m < m1; ++m) {
                float* T = tiles0 + c_tgt_tile[m] * TILE_FLOATS;
                const float cf = c_tgt_coef[m];
#pragma unroll
                for (int jj = 0; jj < 4; ++jj) {
                    const int off = ((c0 + jj) << 7) + r0;
                    float4* p = reinterpret_cast<float4*>(T + off);
                    float4 tv = *p;
                    tv.x = fmaf(cf, kv[jj][0], tv.x);
                    tv.y = fmaf(cf, kv[jj][1], tv.y);
                    tv.z = fmaf(cf, kv[jj][2], tv.z);
                    tv.w = fmaf(cf, kv[jj][3], tv.w);
                    *p = tv;
                }
            }
            __syncthreads();
        }
        // XN now holds x_{t+1}. FSAL: its dynamics value is k0 of the next step.
        if (step < 7) {
            dyn_stage(XN, WG, bgr, r0, c0, kv);
            __syncthreads();
        }
    }

    // ---- output: spike = ((x_final - 0.3) > 0) ? 1 : 0 ----
    for (int idx = t; idx < TROWS * DIM; idx += NTHREADS) {
        int r = idx >> 6, c = idx & 63;
        int row = row0 + r;
        if (row < batch)
            gout[row * DIM + c] = ((XN[(c << 7) + r] - 0.3f) > 0.f) ? 1.f : 0.f;
    }
}

extern "C" void kernel_launch(void* const* d_in, const int* in_sizes, int n_in,
                              void* d_out, int out_size)
{
    const float* x  = (const float*)d_in[0];
    const float* W  = (const float*)d_in[1];
    const float* Wg = (const float*)d_in[2];
    const float* bg = (const float*)d_in[3];
    float* out = (float*)d_out;
    const int batch = in_sizes[0] / DIM;

    cudaFuncSetAttribute(lif_dopri5_kernel,
                         cudaFuncAttributeMaxDynamicSharedMemorySize, SMEM_BYTES);
    const int grid = (batch + TROWS - 1) / TROWS;
    lif_dopri5_kernel<<<grid, NTHREADS, SMEM_BYTES>>>(x, W, Wg, bg, out, batch);
}

// round 9
// speedup vs baseline: 1.2201x; 1.2201x over previous
#include <cuda_runtime.h>
#include <math.h>

// LIFNeuron: spike( dopri5(x; dx = gelu(xW) * 1/(1+sigmoid(xWg+bg)), 8 fixed steps) - 0.3 )
//
// Round 2 kernel, eighth submission (rounds 2-8 hit GPU broker timeouts; no HW data yet):
// dual-GEMM (W | Wg) packed into fma.rn.f32x2. Weights interleaved in smem
// as (W,Wg) pairs so the B operand is naturally packed; accumulators are (au,av)
// pairs; A operand duplicated per row with one mov.b64 {r,r}. Per-lane results are
// bitwise identical to the scalar-FFMA round-1 kernel.

#define DIM 64
#define TROWS 128
#define NTHREADS 512
#define TILE_FLOATS (DIM * 128)            // 8192 floats per tile
#define SMEM_FLOATS (TILE_FLOATS * 7)      // WG(interleaved) + 6 state tiles
#define SMEM_BYTES  (SMEM_FLOATS * 4)      // 229376 bytes

typedef unsigned long long ull;

__device__ __forceinline__ ull dup_f2(float x) {
    ull r; asm("mov.b64 %0, {%1, %1};" : "=l"(r) : "f"(x)); return r;
}
__device__ __forceinline__ ull fma2(ull a, ull b, ull c) {
    ull d; asm("fma.rn.f32x2 %0, %1, %2, %3;" : "=l"(d) : "l"(a), "l"(b), "l"(c)); return d;
}
__device__ __forceinline__ float2 unpk_f2(ull p) {
    float2 o; asm("mov.b64 {%0, %1}, %2;" : "=f"(o.x), "=f"(o.y) : "l"(p)); return o;
}

// h = 1/8 exact; coefficients fp32-rounded exactly as numpy float32, scaled by 2^-3.
__constant__ float c_s0[6] = {
    0.125f * (float)(1.0/5.0),
    0.125f * (float)(3.0/40.0),
    0.125f * (float)(44.0/45.0),
    0.125f * (float)(19372.0/6561.0),
    0.125f * (float)(9017.0/3168.0),
    0.125f * (float)(35.0/384.0)
};
__constant__ int c_tgt_tile[14] = {1,2,3,4, 2,3,4,5, 3,4,5, 4,5, 5};
__constant__ float c_tgt_coef[14] = {
    0.125f * (float)(9.0/40.0),
    0.125f * (float)(-56.0/15.0),
    0.125f * (float)(-25360.0/2187.0),
    0.125f * (float)(-355.0/33.0),

    0.125f * (float)(32.0/9.0),
    0.125f * (float)(64448.0/6561.0),
    0.125f * (float)(46732.0/5247.0),
    0.125f * (float)(500.0/1113.0),

    0.125f * (float)(-212.0/729.0),
    0.125f * (float)(49.0/176.0),
    0.125f * (float)(125.0/192.0),

    0.125f * (float)(-5103.0/18656.0),
    0.125f * (float)(-2187.0/6784.0),

    0.125f * (float)(11.0/84.0)
};
__constant__ int c_seg[6] = {0, 4, 8, 11, 13, 14};

// One dynamics evaluation for this thread's 4-row x 4-col microtile.
// src: state tile [dim][row] (64 x 128). wgi: interleaved weights, wgi[k*128 + 2c] = W[k][c],
// wgi[k*128 + 2c + 1] = Wg[k][c]. kv[j][i] = k value at dim (c0+j), row (r0+i).
__device__ __forceinline__ void dyn_stage(const float* src, const float* wgi,
                                          const float* bgr, int r0, int c0,
                                          float kv[4][4])
{
    ull acc[4][4];
#pragma unroll
    for (int i = 0; i < 4; ++i)
#pragma unroll
        for (int j = 0; j < 4; ++j) acc[i][j] = 0ULL;

    const float* pa = src + r0;
    const ulonglong2* pb = reinterpret_cast<const ulonglong2*>(wgi + 2 * c0);
    // row stride of wgi in ulonglong2 units: 128 floats = 32 ulonglong2

#pragma unroll 4
    for (int k = 0; k < DIM; ++k) {
        float4 a = *reinterpret_cast<const float4*>(pa + (k << 7));
        ulonglong2 b0 = pb[(k << 5)];       // (u,v) pairs for cols c0, c0+1
        ulonglong2 b1 = pb[(k << 5) + 1];   // cols c0+2, c0+3
        ull ap[4];
        ap[0] = dup_f2(a.x); ap[1] = dup_f2(a.y);
        ap[2] = dup_f2(a.z); ap[3] = dup_f2(a.w);
        ull bp[4] = {b0.x, b0.y, b1.x, b1.y};
#pragma unroll
        for (int i = 0; i < 4; ++i)
#pragma unroll
            for (int j = 0; j < 4; ++j)
                acc[i][j] = fma2(ap[i], bp[j], acc[i][j]);
    }

#pragma unroll
    for (int j = 0; j < 4; ++j) {
        const float b = bgr[j];
#pragma unroll
        for (int i = 0; i < 4; ++i) {
            float2 uv = unpk_f2(acc[i][j]);
            float u = uv.x;
            float v = uv.y + b;
            float e  = expf(-v);
            float tf = (1.f + e) / (2.f + e);   // == 1/(1+sigmoid(v)), one division
            float g  = 0.5f * (u * (erff(u * 0.70710678118654752440f) + 1.f));
            kv[j][i] = g * tf;
        }
    }
}

__global__ void __launch_bounds__(NTHREADS, 1)
lif_dopri5_kernel(const float* __restrict__ gx, const float* __restrict__ gW,
                  const float* __restrict__ gWg, const float* __restrict__ gbg,
                  float* __restrict__ gout, int batch)
{
    extern __shared__ float smem[];
    float* WG = smem;                           // interleaved (W,Wg) [64][128]
    float* tiles0 = smem + TILE_FLOATS;         // 5 stage-state tiles, [dim][row]
    float* XN = tiles0 + 5 * TILE_FLOATS;       // running x_new / FSAL base

    const int t  = threadIdx.x;
    const int c0 = (t >> 5) << 2;               // 4 dims per thread (warp-uniform)
    const int r0 = (t & 31) << 2;               // 4 rows per thread (conflict-free LDS.128)
    const int row0 = blockIdx.x * TROWS;

    // Load interleaved weight tile: WG[k*128 + 2c] = W[k][c]; +1 = Wg[k][c]
    for (int idx = t; idx < DIM * 128; idx += NTHREADS) {
        int k = idx >> 7, c2 = idx & 127, c = c2 >> 1;
        WG[idx] = (c2 & 1) ? gWg[k * DIM + c] : gW[k * DIM + c];
    }
    float bgr[4];
    {
        float4 b4 = reinterpret_cast<const float4*>(gbg)[c0 >> 2];
        bgr[0] = b4.x; bgr[1] = b4.y; bgr[2] = b4.z; bgr[3] = b4.w;
    }
    // Load x (transposed) into XN
    for (int idx = t; idx < TROWS * DIM; idx += NTHREADS) {
        int r = idx >> 6, c = idx & 63;
        int row = row0 + r;
        XN[(c << 7) + r] = (row < batch) ? gx[row * DIM + c] : 0.f;
    }
    __syncthreads();

    float kv[4][4];
    // k0 at t = 0 (FSAL seed)
    dyn_stage(XN, WG, bgr, r0, c0, kv);
    __syncthreads();

    for (int step = 0; step < 8; ++step) {
        // ---- stage-0 epilogue: S_i = x + h*a_i0*k0 (i=1..5), XN = x + h*b0*k0 ----
#pragma unroll
        for (int jj = 0; jj < 4; ++jj) {
            const int off = ((c0 + jj) << 7) + r0;
            float4 x4 = *reinterpret_cast<float4*>(XN + off);
#pragma unroll
            for (int m = 0; m < 5; ++m) {
                const float cf = c_s0[m];
                float4 tv;
                tv.x = fmaf(cf, kv[jj][0], x4.x);
                tv.y = fmaf(cf, kv[jj][1], x4.y);
                tv.z = fmaf(cf, kv[jj][2], x4.z);
                tv.w = fmaf(cf, kv[jj][3], x4.w);
                *reinterpret_cast<float4*>(tiles0 + m * TILE_FLOATS + off) = tv;
            }
            {
                const float cf = c_s0[5];
                float4 tv;
                tv.x = fmaf(cf, kv[jj][0], x4.x);
                tv.y = fmaf(cf, kv[jj][1], x4.y);
                tv.z = fmaf(cf, kv[jj][2], x4.z);
                tv.w = fmaf(cf, kv[jj][3], x4.w);
                *reinterpret_cast<float4*>(XN + off) = tv;
            }
        }
        __syncthreads();

        // ---- stages 1..5 ----
        for (int j = 1; j <= 5; ++j) {
            dyn_stage(tiles0 + (j - 1) * TILE_FLOATS, WG, bgr, r0, c0, kv);
            const int m1 = c_seg[j];
            for (int m = c_seg[j - 1]; m < m1; ++m) {
                float* T = tiles0 + c_tgt_tile[m] * TILE_FLOATS;
                const float cf = c_tgt_coef[m];
#pragma unroll
                for (int jj = 0; jj < 4; ++jj) {
                    const int off = ((c0 + jj) << 7) + r0;
                    float4* p = reinterpret_cast<float4*>(T + off);
                    float4 tv = *p;
                    tv.x = fmaf(cf, kv[jj][0], tv.x);
                    tv.y = fmaf(cf, kv[jj][1], tv.y);
                    tv.z = fmaf(cf, kv[jj][2], tv.z);
                    tv.w = fmaf(cf, kv[jj][3], tv.w);
                    *p = tv;
                }
            }
            __syncthreads();
        }
        // XN now holds x_{t+1}; FSAL: its dynamics value is k0 of the next step.
        if (step < 7) {
            dyn_stage(XN, WG, bgr, r0, c0, kv);
            __syncthreads();
        }
    }

    // ---- output: spike = ((x_final - 0.3) > 0) ? 1 : 0 ----
    for (int idx = t; idx < TROWS * DIM; idx += NTHREADS) {
        int r = idx >> 6, c = idx & 63;
        int row = row0 + r;
        if (row < batch)
            gout[row * DIM + c] = ((XN[(c << 7) + r] - 0.3f) > 0.f) ? 1.f : 0.f;
    }
}

extern "C" void kernel_launch(void* const* d_in, const int* in_sizes, int n_in,
                              void* d_out, int out_size)
{
    const float* x  = (const float*)d_in[0];
    const float* W  = (const float*)d_in[1];
    const float* Wg = (const float*)d_in[2];
    const float* bg = (const float*)d_in[3];
    float* out = (float*)d_out;
    const int batch = in_sizes[0] / DIM;

    cudaFuncSetAttribute(lif_dopri5_kernel,
                         cudaFuncAttributeMaxDynamicSharedMemorySize, SMEM_BYTES);
    const int grid = (batch + TROWS - 1) / TROWS;
    lif_dopri5_kernel<<<grid, NTHREADS, SMEM_BYTES>>>(x, W, Wg, bg, out, batch);
}

// round 17
// speedup vs baseline: 1.3367x; 1.0956x over previous
#include <cuda_runtime.h>
#include <math.h>

// LIFNeuron: spike( dopri5(x; dx = gelu(xW) * 1/(1+sigmoid(xWg+bg)), 8 fixed steps) - 0.3 )
//
// Round 10 kernel, eighth submission (rounds 10-16 hit GPU broker timeouts):
// R9 winner (f32x2 dual-GEMM, 19.98ms) + fast-math epilogue.
// Single change vs R9: expf -> __expf, division -> __fdividef in the dynamics
// epilogue (the transcendental chain was ~35% of fma-pipe work). erff stays precise.

#define DIM 64
#define TROWS 128
#define NTHREADS 512
#define TILE_FLOATS (DIM * 128)            // 8192 floats per tile
#define SMEM_FLOATS (TILE_FLOATS * 7)      // WG(interleaved) + 6 state tiles
#define SMEM_BYTES  (SMEM_FLOATS * 4)      // 229376 bytes

typedef unsigned long long ull;

__device__ __forceinline__ ull dup_f2(float x) {
    ull r; asm("mov.b64 %0, {%1, %1};" : "=l"(r) : "f"(x)); return r;
}
__device__ __forceinline__ ull fma2(ull a, ull b, ull c) {
    ull d; asm("fma.rn.f32x2 %0, %1, %2, %3;" : "=l"(d) : "l"(a), "l"(b), "l"(c)); return d;
}
__device__ __forceinline__ float2 unpk_f2(ull p) {
    float2 o; asm("mov.b64 {%0, %1}, %2;" : "=f"(o.x), "=f"(o.y) : "l"(p)); return o;
}

// h = 1/8 exact; coefficients fp32-rounded exactly as numpy float32, scaled by 2^-3.
__constant__ float c_s0[6] = {
    0.125f * (float)(1.0/5.0),
    0.125f * (float)(3.0/40.0),
    0.125f * (float)(44.0/45.0),
    0.125f * (float)(19372.0/6561.0),
    0.125f * (float)(9017.0/3168.0),
    0.125f * (float)(35.0/384.0)
};
__constant__ int c_tgt_tile[14] = {1,2,3,4, 2,3,4,5, 3,4,5, 4,5, 5};
__constant__ float c_tgt_coef[14] = {
    0.125f * (float)(9.0/40.0),
    0.125f * (float)(-56.0/15.0),
    0.125f * (float)(-25360.0/2187.0),
    0.125f * (float)(-355.0/33.0),

    0.125f * (float)(32.0/9.0),
    0.125f * (float)(64448.0/6561.0),
    0.125f * (float)(46732.0/5247.0),
    0.125f * (float)(500.0/1113.0),

    0.125f * (float)(-212.0/729.0),
    0.125f * (float)(49.0/176.0),
    0.125f * (float)(125.0/192.0),

    0.125f * (float)(-5103.0/18656.0),
    0.125f * (float)(-2187.0/6784.0),

    0.125f * (float)(11.0/84.0)
};
__constant__ int c_seg[6] = {0, 4, 8, 11, 13, 14};

// One dynamics evaluation for this thread's 4-row x 4-col microtile.
// src: state tile [dim][row] (64 x 128). wgi: interleaved weights, wgi[k*128 + 2c] = W[k][c],
// wgi[k*128 + 2c + 1] = Wg[k][c]. kv[j][i] = k value at dim (c0+j), row (r0+i).
__device__ __forceinline__ void dyn_stage(const float* src, const float* wgi,
                                          const float* bgr, int r0, int c0,
                                          float kv[4][4])
{
    ull acc[4][4];
#pragma unroll
    for (int i = 0; i < 4; ++i)
#pragma unroll
        for (int j = 0; j < 4; ++j) acc[i][j] = 0ULL;

    const float* pa = src + r0;
    const ulonglong2* pb = reinterpret_cast<const ulonglong2*>(wgi + 2 * c0);
    // row stride of wgi in ulonglong2 units: 128 floats = 32 ulonglong2

#pragma unroll 4
    for (int k = 0; k < DIM; ++k) {
        float4 a = *reinterpret_cast<const float4*>(pa + (k << 7));
        ulonglong2 b0 = pb[(k << 5)];       // (u,v) pairs for cols c0, c0+1
        ulonglong2 b1 = pb[(k << 5) + 1];   // cols c0+2, c0+3
        ull ap[4];
        ap[0] = dup_f2(a.x); ap[1] = dup_f2(a.y);
        ap[2] = dup_f2(a.z); ap[3] = dup_f2(a.w);
        ull bp[4] = {b0.x, b0.y, b1.x, b1.y};
#pragma unroll
        for (int i = 0; i < 4; ++i)
#pragma unroll
            for (int j = 0; j < 4; ++j)
                acc[i][j] = fma2(ap[i], bp[j], acc[i][j]);
    }

#pragma unroll
    for (int j = 0; j < 4; ++j) {
        const float b = bgr[j];
#pragma unroll
        for (int i = 0; i < 4; ++i) {
            float2 uv = unpk_f2(acc[i][j]);
            float u = uv.x;
            float v = uv.y + b;
            float e  = __expf(-v);                          // fast exp (MUFU.EX2)
            float tf = __fdividef(1.f + e, 2.f + e);        // == 1/(1+sigmoid(v))
            float g  = 0.5f * (u * (erff(u * 0.70710678118654752440f) + 1.f));
            kv[j][i] = g * tf;
        }
    }
}

__global__ void __launch_bounds__(NTHREADS, 1)
lif_dopri5_kernel(const float* __restrict__ gx, const float* __restrict__ gW,
                  const float* __restrict__ gWg, const float* __restrict__ gbg,
                  float* __restrict__ gout, int batch)
{
    extern __shared__ float smem[];
    float* WG = smem;                           // interleaved (W,Wg) [64][128]
    float* tiles0 = smem + TILE_FLOATS;         // 5 stage-state tiles, [dim][row]
    float* XN = tiles0 + 5 * TILE_FLOATS;       // running x_new / FSAL base

    const int t  = threadIdx.x;
    const int c0 = (t >> 5) << 2;               // 4 dims per thread (warp-uniform)
    const int r0 = (t & 31) << 2;               // 4 rows per thread (conflict-free LDS.128)
    const int row0 = blockIdx.x * TROWS;

    // Load interleaved weight tile: WG[k*128 + 2c] = W[k][c]; +1 = Wg[k][c]
    for (int idx = t; idx < DIM * 128; idx += NTHREADS) {
        int k = idx >> 7, c2 = idx & 127, c = c2 >> 1;
        WG[idx] = (c2 & 1) ? gWg[k * DIM + c] : gW[k * DIM + c];
    }
    float bgr[4];
    {
        float4 b4 = reinterpret_cast<const float4*>(gbg)[c0 >> 2];
        bgr[0] = b4.x; bgr[1] = b4.y; bgr[2] = b4.z; bgr[3] = b4.w;
    }
    // Load x (transposed) into XN
    for (int idx = t; idx < TROWS * DIM; idx += NTHREADS) {
        int r = idx >> 6, c = idx & 63;
        int row = row0 + r;
        XN[(c << 7) + r] = (row < batch) ? gx[row * DIM + c] : 0.f;
    }
    __syncthreads();

    float kv[4][4];
    // k0 at t = 0 (FSAL seed)
    dyn_stage(XN, WG, bgr, r0, c0, kv);
    __syncthreads();

    for (int step = 0; step < 8; ++step) {
        // ---- stage-0 epilogue: S_i = x + h*a_i0*k0 (i=1..5), XN = x + h*b0*k0 ----
#pragma unroll
        for (int jj = 0; jj < 4; ++jj) {
            const int off = ((c0 + jj) << 7) + r0;
            float4 x4 = *reinterpret_cast<float4*>(XN + off);
#pragma unroll
            for (int m = 0; m < 5; ++m) {
                const float cf = c_s0[m];
                float4 tv;
                tv.x = fmaf(cf, kv[jj][0], x4.x);
                tv.y = fmaf(cf, kv[jj][1], x4.y);
                tv.z = fmaf(cf, kv[jj][2], x4.z);
                tv.w = fmaf(cf, kv[jj][3], x4.w);
                *reinterpret_cast<float4*>(tiles0 + m * TILE_FLOATS + off) = tv;
            }
            {
                const float cf = c_s0[5];
                float4 tv;
                tv.x = fmaf(cf, kv[jj][0], x4.x);
                tv.y = fmaf(cf, kv[jj][1], x4.y);
                tv.z = fmaf(cf, kv[jj][2], x4.z);
                tv.w = fmaf(cf, kv[jj][3], x4.w);
                *reinterpret_cast<float4*>(XN + off) = tv;
            }
        }
        __syncthreads();

        // ---- stages 1..5 ----
        for (int j = 1; j <= 5; ++j) {
            dyn_stage(tiles0 + (j - 1) * TILE_FLOATS, WG, bgr, r0, c0, kv);
            const int m1 = c_seg[j];
            for (int m = c_seg[j - 1]; m < m1; ++m) {
                float* T = tiles0 + c_tgt_tile[m] * TILE_FLOATS;
                const float cf = c_tgt_coef[m];
#pragma unroll
                for (int jj = 0; jj < 4; ++jj) {
                    const int off = ((c0 + jj) << 7) + r0;
                    float4* p = reinterpret_cast<float4*>(T + off);
                    float4 tv = *p;
                    tv.x = fmaf(cf, kv[jj][0], tv.x);
                    tv.y = fmaf(cf, kv[jj][1], tv.y);
                    tv.z = fmaf(cf, kv[jj][2], tv.z);
                    tv.w = fmaf(cf, kv[jj][3], tv.w);
                    *p = tv;
                }
            }
            __syncthreads();
        }
        // XN now holds x_{t+1}; FSAL: its dynamics value is k0 of the next step.
        if (step < 7) {
            dyn_stage(XN, WG, bgr, r0, c0, kv);
            __syncthreads();
        }
    }

    // ---- output: spike = ((x_final - 0.3) > 0) ? 1 : 0 ----
    for (int idx = t; idx < TROWS * DIM; idx += NTHREADS) {
        int r = idx >> 6, c = idx & 63;
        int row = row0 + r;
        if (row < batch)
            gout[row * DIM + c] = ((XN[(c << 7) + r] - 0.3f) > 0.f) ? 1.f : 0.f;
    }
}

extern "C" void kernel_launch(void* const* d_in, const int* in_sizes, int n_in,
                              void* d_out, int out_size)
{
    const float* x  = (const float*)d_in[0];
    const float* W  = (const float*)d_in[1];
    const float* Wg = (const float*)d_in[2];
    const float* bg = (const float*)d_in[3];
    float* out = (float*)d_out;
    const int batch = in_sizes[0] / DIM;

    cudaFuncSetAttribute(lif_dopri5_kernel,
                         cudaFuncAttributeMaxDynamicSharedMemorySize, SMEM_BYTES);
    const int grid = (batch + TROWS - 1) / TROWS;
    lif_dopri5_kernel<<<grid, NTHREADS, SMEM_BYTES>>>(x, W, Wg, bg, out, batch);
}